// round 1
// baseline (speedup 1.0000x reference)
#include <cuda_runtime.h>
#include <cuda_bf16.h>
#include <math.h>

// ---------------------------------------------------------------------------
// Problem constants
// ---------------------------------------------------------------------------
#define BB 512
#define VV 6890
#define NJ 24
#define NBETA 10
#define NP 207
#define NJO 19
#define VC (VV*3)              // 20670
#define KTOT 217               // 207 posedirs rows + 10 shapes rows
#define KPAD 224               // padded to 7*32
#define VERT_OFF 0
#define JNT_OFF  (BB*VC)                  // 10583040
#define ROT_OFF  (JNT_OFF + BB*NJO*3)     // 10612224

__device__ __constant__ int cPAR[NJ] = {0,0,0,0,1,2,3,4,5,6,7,8,9,9,9,12,13,14,16,17,18,19,20,21};

// ---------------------------------------------------------------------------
// Scratch (device globals; no allocation)
// ---------------------------------------------------------------------------
__device__ float g_pfT[KPAD * BB];        // pose-feature+beta, transposed [k][b]
__device__ float g_A[BB * NJ * 12];       // A' 3x4 per (b,j), row-major, float4-friendly
__device__ float g_jmp[NJ * 8 * 33];      // partial joint-regressor precompute
__device__ float g_jm[NJ * 33];           // reduced: [j][0..2]=base, [j][3+3k+c]=M
__device__ float g_jpart[BB * 14 * 57];   // joint output partials

// ---------------------------------------------------------------------------
// Kernel 0: per-launch precompute  base[j,c] = sum_v vt[v,c]*SR[v,j],
//           M[k,j,c] = sum_v shapes[k,3v+c]*SR[v,j]   (batch-independent)
// grid (24 joints, 8 V-chunks), 128 threads
// ---------------------------------------------------------------------------
__global__ void __launch_bounds__(128) k_jm(const float* __restrict__ vt,
                                            const float* __restrict__ shp,
                                            const float* __restrict__ sr)
{
    int j = blockIdx.x, part = blockIdx.y;
    int vs = part * 862;
    int ve = vs + 862; if (ve > VV) ve = VV;

    float acc[33];
    #pragma unroll
    for (int i = 0; i < 33; ++i) acc[i] = 0.f;

    for (int v = vs + threadIdx.x; v < ve; v += 128) {
        float w = sr[v * NJ + j];
        acc[0] += vt[v*3+0] * w;
        acc[1] += vt[v*3+1] * w;
        acc[2] += vt[v*3+2] * w;
        #pragma unroll
        for (int k = 0; k < NBETA; ++k) {
            const float* s = shp + k * VC + v * 3;
            acc[3+k*3+0] += s[0] * w;
            acc[3+k*3+1] += s[1] * w;
            acc[3+k*3+2] += s[2] * w;
        }
    }
    // warp reduce
    #pragma unroll
    for (int m = 16; m > 0; m >>= 1)
        #pragma unroll
        for (int i = 0; i < 33; ++i)
            acc[i] += __shfl_xor_sync(0xffffffffu, acc[i], m);

    __shared__ float s[4][33];
    int wid = threadIdx.x >> 5, lane = threadIdx.x & 31;
    if (lane == 0)
        #pragma unroll
        for (int i = 0; i < 33; ++i) s[wid][i] = acc[i];
    __syncthreads();
    if (threadIdx.x < 33) {
        float t = s[0][threadIdx.x] + s[1][threadIdx.x] + s[2][threadIdx.x] + s[3][threadIdx.x];
        g_jmp[(j*8 + part)*33 + threadIdx.x] = t;
    }
}

__global__ void k_jmred()
{
    int i = blockIdx.x * blockDim.x + threadIdx.x;
    if (i < NJ * 33) {
        int jj = i / 33, r = i % 33;
        float t = 0.f;
        #pragma unroll
        for (int p = 0; p < 8; ++p) t += g_jmp[(jj*8 + p)*33 + r];
        g_jm[i] = t;
    }
}

// ---------------------------------------------------------------------------
// Kernel 1a: Rodrigues per (b,j). Writes rot output + pose_feature rows.
// ---------------------------------------------------------------------------
__global__ void k_rot(const float* __restrict__ inp, float* __restrict__ out)
{
    int i = blockIdx.x * blockDim.x + threadIdx.x;
    if (i >= BB * NJ) return;
    int b = i / NJ, j = i % NJ;
    float rx = inp[b*82 + j*3 + 0];
    float ry = inp[b*82 + j*3 + 1];
    float rz = inp[b*82 + j*3 + 2];
    float ax = rx + 1e-8f, ay = ry + 1e-8f, az = rz + 1e-8f;
    float ang = sqrtf(ax*ax + ay*ay + az*az);
    float inv = 1.0f / ang;
    float nx = rx * inv, ny = ry * inv, nz = rz * inv;
    float c = cosf(ang), sn = sinf(ang), ic = 1.0f - c;
    float R[9];
    R[0] = c + ic*nx*nx;     R[1] = ic*nx*ny - sn*nz; R[2] = ic*nx*nz + sn*ny;
    R[3] = ic*ny*nx + sn*nz; R[4] = c + ic*ny*ny;     R[5] = ic*ny*nz - sn*nx;
    R[6] = ic*nz*nx - sn*ny; R[7] = ic*nz*ny + sn*nx; R[8] = c + ic*nz*nz;

    float* ro = out + ROT_OFF + b*(NJ*9) + j*9;
    #pragma unroll
    for (int e = 0; e < 9; ++e) ro[e] = R[e];

    if (j > 0) {
        int base = (j-1) * 9;
        #pragma unroll
        for (int e = 0; e < 9; ++e) {
            float v = R[e] - ((e == 0 || e == 4 || e == 8) ? 1.0f : 0.0f);
            g_pfT[(base + e) * BB + b] = v;
        }
    }
}

// ---------------------------------------------------------------------------
// Kernel 1b: per-batch: rest joints (from g_jm), kinematic chain, A' output,
//            beta rows + zero pad of pfT.
// ---------------------------------------------------------------------------
__global__ void __launch_bounds__(128) k_chain(const float* __restrict__ inp,
                                               const float* __restrict__ out)
{
    __shared__ float s_jm[NJ * 33];
    for (int i = threadIdx.x; i < NJ*33; i += 128) s_jm[i] = g_jm[i];
    __syncthreads();

    int b = blockIdx.x * 128 + threadIdx.x;
    if (b >= BB) return;

    float bet[NBETA];
    #pragma unroll
    for (int k = 0; k < NBETA; ++k) bet[k] = inp[b*82 + 72 + k];

    float J[NJ][3];
    #pragma unroll
    for (int j = 0; j < NJ; ++j)
        #pragma unroll
        for (int c = 0; c < 3; ++c) {
            float t = s_jm[j*33 + c];
            #pragma unroll
            for (int k = 0; k < NBETA; ++k)
                t = fmaf(bet[k], s_jm[j*33 + 3 + k*3 + c], t);
            J[j][c] = t;
        }

    const float* Rb = out + ROT_OFF + b*(NJ*9);
    float Rw[NJ][9], tw[NJ][3];
    #pragma unroll
    for (int e = 0; e < 9; ++e) Rw[0][e] = Rb[e];
    tw[0][0] = J[0][0]; tw[0][1] = J[0][1]; tw[0][2] = J[0][2];

    #pragma unroll
    for (int j = 1; j < NJ; ++j) {
        int p = cPAR[j];
        float Rj[9];
        #pragma unroll
        for (int e = 0; e < 9; ++e) Rj[e] = Rb[j*9 + e];
        float t0 = J[j][0] - J[p][0];
        float t1 = J[j][1] - J[p][1];
        float t2 = J[j][2] - J[p][2];
        #pragma unroll
        for (int r = 0; r < 3; ++r) {
            float p0 = Rw[p][r*3+0], p1 = Rw[p][r*3+1], p2 = Rw[p][r*3+2];
            Rw[j][r*3+0] = p0*Rj[0] + p1*Rj[3] + p2*Rj[6];
            Rw[j][r*3+1] = p0*Rj[1] + p1*Rj[4] + p2*Rj[7];
            Rw[j][r*3+2] = p0*Rj[2] + p1*Rj[5] + p2*Rj[8];
            tw[j][r] = p0*t0 + p1*t1 + p2*t2 + tw[p][r];
        }
    }

    float* Ao = g_A + b * (NJ*12);
    #pragma unroll
    for (int j = 0; j < NJ; ++j)
        #pragma unroll
        for (int r = 0; r < 3; ++r) {
            float tp = tw[j][r] - (Rw[j][r*3+0]*J[j][0] + Rw[j][r*3+1]*J[j][1] + Rw[j][r*3+2]*J[j][2]);
            Ao[j*12 + r*4 + 0] = Rw[j][r*3+0];
            Ao[j*12 + r*4 + 1] = Rw[j][r*3+1];
            Ao[j*12 + r*4 + 2] = Rw[j][r*3+2];
            Ao[j*12 + r*4 + 3] = tp;
        }

    #pragma unroll
    for (int k = 0; k < NBETA; ++k) g_pfT[(NP + k)*BB + b] = bet[k];
    #pragma unroll
    for (int k = KTOT; k < KPAD; ++k) g_pfT[k*BB + b] = 0.0f;
}

// ---------------------------------------------------------------------------
// Kernel 2: THE big one. Fused  v_posed = pfT^T @ [posedirs;shapes] + vt
//           then LBS skinning -> vertices, all in registers/smem.
// Tile: 32 batches x 32 vertices (96 cols). 128 threads:
//   tv = tid&15 (vertex pair), tb = tid>>4 (batch quad)
//   each thread: 4 batches x 2 vertices = 24 accumulators.
// ---------------------------------------------------------------------------
__global__ void __launch_bounds__(128) k_main(const float* __restrict__ posedirs,
                                              const float* __restrict__ shapes,
                                              const float* __restrict__ lbs,
                                              const float* __restrict__ vtempl,
                                              float* __restrict__ out)
{
    __shared__ float smem[10080];   // 40.3 KB, unioned: mainloop {pf,pd} / epilogue {A,w,vt}

    const int vtile = blockIdx.x;
    const int b0 = blockIdx.y * 32;
    const int col0 = vtile * 96;
    const int v0 = vtile * 32;
    const int tid = threadIdx.x;
    const int tv = tid & 15;
    const int tb = tid >> 4;

    float acc[24];
    #pragma unroll
    for (int i = 0; i < 24; ++i) acc[i] = 0.f;

    float* s_pf = smem;           // [32][32]
    float* s_pd = smem + 1024;    // [32][96]

    for (int kt = 0; kt < 7; ++kt) {
        // pose-feature tile: 32 k-rows x 32 batches, as float4
        #pragma unroll
        for (int i = tid; i < 256; i += 128) {
            int k = i >> 3, q = i & 7;
            reinterpret_cast<float4*>(s_pf)[i] =
                *reinterpret_cast<const float4*>(&g_pfT[(kt*32 + k)*BB + b0 + q*4]);
        }
        // B tile: 32 k-rows x 96 cols, as float2 (rows are 8B aligned)
        #pragma unroll
        for (int i = tid; i < 1536; i += 128) {
            int k = i / 48, q = i % 48;
            int kg = kt*32 + k;
            int cg = col0 + q*2;
            float2 val = make_float2(0.f, 0.f);
            if (cg < VC) {
                if (kg < NP)
                    val = *reinterpret_cast<const float2*>(posedirs + (size_t)kg*VC + cg);
                else if (kg < KTOT)
                    val = *reinterpret_cast<const float2*>(shapes + (size_t)(kg-NP)*VC + cg);
            }
            reinterpret_cast<float2*>(s_pd)[i] = val;
        }
        __syncthreads();

        #pragma unroll
        for (int k = 0; k < 32; ++k) {
            const float4 p = *reinterpret_cast<const float4*>(&s_pf[k*32 + (tb<<2)]);
            const float2 d0 = *reinterpret_cast<const float2*>(&s_pd[k*96 + tv*6 + 0]);
            const float2 d1 = *reinterpret_cast<const float2*>(&s_pd[k*96 + tv*6 + 2]);
            const float2 d2 = *reinterpret_cast<const float2*>(&s_pd[k*96 + tv*6 + 4]);
            float pb[4] = {p.x, p.y, p.z, p.w};
            float dv[6] = {d0.x, d0.y, d1.x, d1.y, d2.x, d2.y};
            #pragma unroll
            for (int bb = 0; bb < 4; ++bb)
                #pragma unroll
                for (int cc = 0; cc < 6; ++cc)
                    acc[bb*6+cc] = fmaf(pb[bb], dv[cc], acc[bb*6+cc]);
        }
        __syncthreads();
    }

    // ---- epilogue: reload smem union with A' (32 batches), weights, template
    float4* sA4 = reinterpret_cast<float4*>(smem);                 // [32][72] float4
    const float4* gA4 = reinterpret_cast<const float4*>(g_A + b0*(NJ*12));
    #pragma unroll
    for (int i = 0; i < 18; ++i) sA4[tid + 128*i] = gA4[tid + 128*i];
    float* s_w  = smem + 9216;   // [32][24]
    float* s_vt = smem + 9984;   // [96]
    #pragma unroll
    for (int i = tid; i < 768; i += 128) {
        int v = v0 + i/24;
        s_w[i] = (v < VV) ? lbs[v*NJ + (i % 24)] : 0.f;
    }
    if (tid < 96) {
        int cg = col0 + tid;
        s_vt[tid] = (cg < VC) ? vtempl[cg] : 0.f;
    }
    __syncthreads();

    #pragma unroll
    for (int bb = 0; bb < 4; ++bb) {
        const int bl = (tb << 2) + bb;
        const float4* Ab = reinterpret_cast<const float4*>(smem) + bl*72;
        float T0[12], T1[12];
        #pragma unroll
        for (int i = 0; i < 12; ++i) { T0[i] = 0.f; T1[i] = 0.f; }
        #pragma unroll
        for (int j = 0; j < NJ; ++j) {
            float4 a0 = Ab[j*3 + 0];
            float4 a1 = Ab[j*3 + 1];
            float4 a2 = Ab[j*3 + 2];
            float w0 = s_w[(tv*2 + 0)*24 + j];
            float w1 = s_w[(tv*2 + 1)*24 + j];
            T0[0] = fmaf(w0, a0.x, T0[0]); T0[1] = fmaf(w0, a0.y, T0[1]);
            T0[2] = fmaf(w0, a0.z, T0[2]); T0[3] = fmaf(w0, a0.w, T0[3]);
            T0[4] = fmaf(w0, a1.x, T0[4]); T0[5] = fmaf(w0, a1.y, T0[5]);
            T0[6] = fmaf(w0, a1.z, T0[6]); T0[7] = fmaf(w0, a1.w, T0[7]);
            T0[8] = fmaf(w0, a2.x, T0[8]); T0[9] = fmaf(w0, a2.y, T0[9]);
            T0[10]= fmaf(w0, a2.z, T0[10]);T0[11]= fmaf(w0, a2.w, T0[11]);
            T1[0] = fmaf(w1, a0.x, T1[0]); T1[1] = fmaf(w1, a0.y, T1[1]);
            T1[2] = fmaf(w1, a0.z, T1[2]); T1[3] = fmaf(w1, a0.w, T1[3]);
            T1[4] = fmaf(w1, a1.x, T1[4]); T1[5] = fmaf(w1, a1.y, T1[5]);
            T1[6] = fmaf(w1, a1.z, T1[6]); T1[7] = fmaf(w1, a1.w, T1[7]);
            T1[8] = fmaf(w1, a2.x, T1[8]); T1[9] = fmaf(w1, a2.y, T1[9]);
            T1[10]= fmaf(w1, a2.z, T1[10]);T1[11]= fmaf(w1, a2.w, T1[11]);
        }
        const int b = b0 + bl;
        {
            int vg = v0 + tv*2;
            if (vg < VV) {
                float x = acc[bb*6+0] + s_vt[tv*6+0];
                float y = acc[bb*6+1] + s_vt[tv*6+1];
                float z = acc[bb*6+2] + s_vt[tv*6+2];
                float* o = out + (size_t)b*VC + vg*3;
                o[0] = T0[0]*x + T0[1]*y + T0[2]*z + T0[3];
                o[1] = T0[4]*x + T0[5]*y + T0[6]*z + T0[7];
                o[2] = T0[8]*x + T0[9]*y + T0[10]*z + T0[11];
            }
        }
        {
            int vg = v0 + tv*2 + 1;
            if (vg < VV) {
                float x = acc[bb*6+3] + s_vt[tv*6+3];
                float y = acc[bb*6+4] + s_vt[tv*6+4];
                float z = acc[bb*6+5] + s_vt[tv*6+5];
                float* o = out + (size_t)b*VC + vg*3;
                o[0] = T1[0]*x + T1[1]*y + T1[2]*z + T1[3];
                o[1] = T1[4]*x + T1[5]*y + T1[6]*z + T1[7];
                o[2] = T1[8]*x + T1[9]*y + T1[10]*z + T1[11];
            }
        }
    }
}

// ---------------------------------------------------------------------------
// Kernel 3a: joints partials. grid (14 V-chunks, 64 batch-tiles of 8), 256 thr.
// Warp = one batch; deterministic chunked reduction (no atomics).
// ---------------------------------------------------------------------------
__global__ void __launch_bounds__(256) k_jnt_part(const float* __restrict__ outv,
                                                  const float* __restrict__ jreg)
{
    __shared__ float s_jr[512 * NJO];
    const int chunk = blockIdx.x;
    const int v0 = chunk * 512;
    for (int i = threadIdx.x; i < 512*NJO; i += 256) {
        int v = v0 + i / NJO;
        s_jr[i] = (v < VV) ? jreg[v*NJO + (i % NJO)] : 0.f;
    }
    __syncthreads();

    const int bl = threadIdx.x >> 5, lane = threadIdx.x & 31;
    const int b = blockIdx.y * 8 + bl;

    float acc[57];
    #pragma unroll
    for (int i = 0; i < 57; ++i) acc[i] = 0.f;

    #pragma unroll 4
    for (int i = 0; i < 16; ++i) {
        int vl = lane + i*32;
        int vg = v0 + vl;
        if (vg < VV) {
            const float* p = outv + (size_t)b*VC + vg*3;
            float x = p[0], y = p[1], z = p[2];
            #pragma unroll
            for (int j = 0; j < NJO; ++j) {
                float r = s_jr[vl*NJO + j];
                acc[j*3+0] = fmaf(r, x, acc[j*3+0]);
                acc[j*3+1] = fmaf(r, y, acc[j*3+1]);
                acc[j*3+2] = fmaf(r, z, acc[j*3+2]);
            }
        }
    }
    #pragma unroll
    for (int m = 16; m > 0; m >>= 1)
        #pragma unroll
        for (int i = 0; i < 57; ++i)
            acc[i] += __shfl_xor_sync(0xffffffffu, acc[i], m);

    if (lane == 0) {
        float* dst = g_jpart + (size_t)(b*14 + chunk)*57;
        #pragma unroll
        for (int i = 0; i < 57; ++i) dst[i] = acc[i];
    }
}

__global__ void k_jnt_red(float* __restrict__ out)
{
    int i = blockIdx.x * blockDim.x + threadIdx.x;
    if (i < BB * 57) {
        int b = i / 57, r = i % 57;
        float t = 0.f;
        #pragma unroll
        for (int p = 0; p < 14; ++p) t += g_jpart[(size_t)(b*14 + p)*57 + r];
        out[JNT_OFF + i] = t;
    }
}

// ---------------------------------------------------------------------------
extern "C" void kernel_launch(void* const* d_in, const int* in_sizes, int n_in,
                              void* d_out, int out_size)
{
    const float* inputs   = (const float*)d_in[0];
    const float* v_templ  = (const float*)d_in[1];
    const float* shapes   = (const float*)d_in[2];
    const float* posedirs = (const float*)d_in[3];
    const float* smpl_reg = (const float*)d_in[4];
    const float* lbs_w    = (const float*)d_in[5];
    const float* joint_rg = (const float*)d_in[6];
    float* out = (float*)d_out;

    // 0: batch-independent joint-regressor precompute (tiny)
    k_jm<<<dim3(NJ, 8), 128>>>(v_templ, shapes, smpl_reg);
    k_jmred<<<4, 256>>>();

    // 1: Rodrigues + pose feature, then kinematic chain + A'
    k_rot<<<(BB*NJ + 255)/256, 256>>>(inputs, out);
    k_chain<<<4, 128>>>(inputs, out);

    // 2: fused blendshape GEMM + LBS skinning -> vertices
    k_main<<<dim3(216, 16), 128>>>(posedirs, shapes, lbs_w, v_templ, out);

    // 3: vertices -> joints (deterministic two-stage reduction)
    k_jnt_part<<<dim3(14, 64), 256>>>(out, joint_rg);
    k_jnt_red<<<(BB*57 + 255)/256, 256>>>(out);
}

// round 2
// speedup vs baseline: 1.1624x; 1.1624x over previous
#include <cuda_runtime.h>
#include <cuda_bf16.h>
#include <math.h>

// ---------------------------------------------------------------------------
// Problem constants
// ---------------------------------------------------------------------------
#define BB 512
#define VV 6890
#define NJ 24
#define NBETA 10
#define NP 207
#define NJO 19
#define VC (VV*3)              // 20670
#define KTOT 217               // 207 posedirs rows + 10 shapes rows
#define KPAD 224               // padded to 7*32
#define JNT_OFF  (BB*VC)                  // 10583040
#define ROT_OFF  (JNT_OFF + BB*NJO*3)     // 10612224

typedef unsigned long long u64;

__device__ __forceinline__ u64 ffma2(u64 a, u64 b, u64 c) {
    u64 d;
    asm("fma.rn.f32x2 %0, %1, %2, %3;" : "=l"(d) : "l"(a), "l"(b), "l"(c));
    return d;
}
__device__ __forceinline__ u64 pack2(float lo, float hi) {
    u64 d;
    asm("mov.b64 %0, {%1, %2};" : "=l"(d) : "f"(lo), "f"(hi));
    return d;
}
__device__ __forceinline__ float2 unpack2(u64 v) {
    float2 f;
    asm("mov.b64 {%0, %1}, %2;" : "=f"(f.x), "=f"(f.y) : "l"(v));
    return f;
}

// ---------------------------------------------------------------------------
// Scratch (device globals; no allocation)
// ---------------------------------------------------------------------------
__device__ float g_pfT[KPAD * BB];        // pose-feature+beta, transposed [k][b]
__device__ float g_A[BB * NJ * 12];       // A' 3x4 per (b,j), row-major
__device__ float g_jmp[NJ * 8 * 33];      // partial joint-regressor precompute
__device__ float g_jm[NJ * 33];           // reduced: [j][0..2]=base, [j][3+3k+c]=M
__device__ float g_jpart[BB * 14 * 57];   // joint output partials

// ---------------------------------------------------------------------------
// Kernel 0: batch-independent precompute for rest joints
// ---------------------------------------------------------------------------
__global__ void __launch_bounds__(128) k_jm(const float* __restrict__ vt,
                                            const float* __restrict__ shp,
                                            const float* __restrict__ sr)
{
    int j = blockIdx.x, part = blockIdx.y;
    int vs = part * 862;
    int ve = vs + 862; if (ve > VV) ve = VV;

    float acc[33];
    #pragma unroll
    for (int i = 0; i < 33; ++i) acc[i] = 0.f;

    for (int v = vs + threadIdx.x; v < ve; v += 128) {
        float w = sr[v * NJ + j];
        acc[0] += vt[v*3+0] * w;
        acc[1] += vt[v*3+1] * w;
        acc[2] += vt[v*3+2] * w;
        #pragma unroll
        for (int k = 0; k < NBETA; ++k) {
            const float* s = shp + k * VC + v * 3;
            acc[3+k*3+0] += s[0] * w;
            acc[3+k*3+1] += s[1] * w;
            acc[3+k*3+2] += s[2] * w;
        }
    }
    #pragma unroll
    for (int m = 16; m > 0; m >>= 1)
        #pragma unroll
        for (int i = 0; i < 33; ++i)
            acc[i] += __shfl_xor_sync(0xffffffffu, acc[i], m);

    __shared__ float s[4][33];
    int wid = threadIdx.x >> 5, lane = threadIdx.x & 31;
    if (lane == 0)
        #pragma unroll
        for (int i = 0; i < 33; ++i) s[wid][i] = acc[i];
    __syncthreads();
    if (threadIdx.x < 33) {
        float t = s[0][threadIdx.x] + s[1][threadIdx.x] + s[2][threadIdx.x] + s[3][threadIdx.x];
        g_jmp[(j*8 + part)*33 + threadIdx.x] = t;
    }
}

__global__ void k_jmred()
{
    int i = blockIdx.x * blockDim.x + threadIdx.x;
    if (i < NJ * 33) {
        int jj = i / 33, r = i % 33;
        float t = 0.f;
        #pragma unroll
        for (int p = 0; p < 8; ++p) t += g_jmp[(jj*8 + p)*33 + r];
        g_jm[i] = t;
    }
}

// ---------------------------------------------------------------------------
// Kernel 1a: Rodrigues per (b,j). Writes rot output + pose_feature rows.
// ---------------------------------------------------------------------------
__global__ void k_rot(const float* __restrict__ inp, float* __restrict__ out)
{
    int i = blockIdx.x * blockDim.x + threadIdx.x;
    if (i >= BB * NJ) return;
    int b = i / NJ, j = i % NJ;
    float rx = inp[b*82 + j*3 + 0];
    float ry = inp[b*82 + j*3 + 1];
    float rz = inp[b*82 + j*3 + 2];
    float ax = rx + 1e-8f, ay = ry + 1e-8f, az = rz + 1e-8f;
    float ang = sqrtf(ax*ax + ay*ay + az*az);
    float inv = 1.0f / ang;
    float nx = rx * inv, ny = ry * inv, nz = rz * inv;
    float c = cosf(ang), sn = sinf(ang), ic = 1.0f - c;
    float R[9];
    R[0] = c + ic*nx*nx;     R[1] = ic*nx*ny - sn*nz; R[2] = ic*nx*nz + sn*ny;
    R[3] = ic*ny*nx + sn*nz; R[4] = c + ic*ny*ny;     R[5] = ic*ny*nz - sn*nx;
    R[6] = ic*nz*nx - sn*ny; R[7] = ic*nz*ny + sn*nx; R[8] = c + ic*nz*nz;

    float* ro = out + ROT_OFF + b*(NJ*9) + j*9;
    #pragma unroll
    for (int e = 0; e < 9; ++e) ro[e] = R[e];

    if (j > 0) {
        int base = (j-1) * 9;
        #pragma unroll
        for (int e = 0; e < 9; ++e) {
            float v = R[e] - ((e == 0 || e == 4 || e == 8) ? 1.0f : 0.0f);
            g_pfT[(base + e) * BB + b] = v;
        }
    }
}

// ---------------------------------------------------------------------------
// Kernel 1b: kinematic chain, one thread per (batch, affine-row).
// Rows of the world transform compose independently:
//   row_r(j) = row_r(parent) * R_j ;  tw_r(j) = row_r(parent)·(J_j-J_p) + tw_r(p)
// 96 threads/block = 32 batches x 3 rows. J staged in smem. ~110 regs (no spill).
// ---------------------------------------------------------------------------
__global__ void __launch_bounds__(96) k_chain(const float* __restrict__ inp,
                                              const float* __restrict__ out)
{
    const int PAR[NJ] = {0,0,0,0,1,2,3,4,5,6,7,8,9,9,9,12,13,14,16,17,18,19,20,21};
    __shared__ float s_jm[NJ * 33];
    __shared__ float sJ[32][NJ][3];

    const int tid = threadIdx.x;
    const int b0 = blockIdx.x * 32;

    for (int i = tid; i < NJ*33; i += 96) s_jm[i] = g_jm[i];
    __syncthreads();

    // rest joints for 32 batches, cooperatively
    for (int i = tid; i < 32*NJ*3; i += 96) {
        int bl = i / 72, rem = i % 72;
        int j = rem / 3, c = rem % 3;
        int b = b0 + bl;
        float t = s_jm[j*33 + c];
        #pragma unroll
        for (int k = 0; k < NBETA; ++k)
            t = fmaf(inp[b*82 + 72 + k], s_jm[j*33 + 3 + k*3 + c], t);
        sJ[bl][j][c] = t;
    }
    __syncthreads();

    const int bl = tid / 3;
    const int r  = tid % 3;
    const int b  = b0 + bl;

    const float* Rb = out + ROT_OFF + b*(NJ*9);

    float row[NJ][3];
    float tw[NJ];
    row[0][0] = Rb[r*3+0]; row[0][1] = Rb[r*3+1]; row[0][2] = Rb[r*3+2];
    tw[0] = sJ[bl][0][r];

    #pragma unroll
    for (int j = 1; j < NJ; ++j) {
        const int p = PAR[j];
        float Rj[9];
        #pragma unroll
        for (int e = 0; e < 9; ++e) Rj[e] = Rb[j*9 + e];
        float t0 = sJ[bl][j][0] - sJ[bl][p][0];
        float t1 = sJ[bl][j][1] - sJ[bl][p][1];
        float t2 = sJ[bl][j][2] - sJ[bl][p][2];
        float p0 = row[p][0], p1 = row[p][1], p2 = row[p][2];
        row[j][0] = p0*Rj[0] + p1*Rj[3] + p2*Rj[6];
        row[j][1] = p0*Rj[1] + p1*Rj[4] + p2*Rj[7];
        row[j][2] = p0*Rj[2] + p1*Rj[5] + p2*Rj[8];
        tw[j] = p0*t0 + p1*t1 + p2*t2 + tw[p];
    }

    float* Ao = g_A + b * (NJ*12);
    #pragma unroll
    for (int j = 0; j < NJ; ++j) {
        float tp = tw[j] - (row[j][0]*sJ[bl][j][0] + row[j][1]*sJ[bl][j][1] + row[j][2]*sJ[bl][j][2]);
        float4 st = make_float4(row[j][0], row[j][1], row[j][2], tp);
        *reinterpret_cast<float4*>(&Ao[j*12 + r*4]) = st;
    }

    if (r == 0) {
        #pragma unroll
        for (int k = 0; k < NBETA; ++k) g_pfT[(NP + k)*BB + b] = inp[b*82 + 72 + k];
        #pragma unroll
        for (int k = KTOT; k < KPAD; ++k) g_pfT[k*BB + b] = 0.0f;
    }
}

// ---------------------------------------------------------------------------
// Kernel 2: fused blendshape GEMM + LBS skinning, packed fp32x2 FMA.
// Tile: 32 batches x 32 vertices. 128 threads, each 4b x 2v.
// Pose-feature tile stored lane-DUPLICATED in smem (u64), so the broadcast
// operand of fma.rn.f32x2 needs no per-iteration pack.
// ---------------------------------------------------------------------------
__global__ void __launch_bounds__(128) k_main(const float* __restrict__ posedirs,
                                              const float* __restrict__ shapes,
                                              const float* __restrict__ lbs,
                                              const float* __restrict__ vtempl,
                                              float* __restrict__ out)
{
    __shared__ __align__(16) float smem[10080];   // union: {pf2(2048f) | pd(3072f)} / {A,w,vt}

    const int vtile = blockIdx.x;
    const int b0 = blockIdx.y * 32;
    const int col0 = vtile * 96;
    const int v0 = vtile * 32;
    const int tid = threadIdx.x;
    const int tv = tid & 15;
    const int tb = tid >> 4;

    u64 acc2[12];
    const u64 z2 = pack2(0.f, 0.f);
    #pragma unroll
    for (int i = 0; i < 12; ++i) acc2[i] = z2;

    u64*   s_pf2 = reinterpret_cast<u64*>(smem);   // [32][32] duplicated pairs
    float* s_pd  = smem + 2048;                    // [32][96]

    for (int kt = 0; kt < 7; ++kt) {
        #pragma unroll
        for (int i = tid; i < 256; i += 128) {
            int k = i >> 3, q = i & 7;
            float4 v = *reinterpret_cast<const float4*>(&g_pfT[(kt*32 + k)*BB + b0 + q*4]);
            u64* dst = s_pf2 + k*32 + q*4;
            dst[0] = pack2(v.x, v.x);
            dst[1] = pack2(v.y, v.y);
            dst[2] = pack2(v.z, v.z);
            dst[3] = pack2(v.w, v.w);
        }
        #pragma unroll
        for (int i = tid; i < 1536; i += 128) {
            int k = i / 48, q = i % 48;
            int kg = kt*32 + k;
            int cg = col0 + q*2;
            float2 val = make_float2(0.f, 0.f);
            if (cg < VC) {
                if (kg < NP)
                    val = *reinterpret_cast<const float2*>(posedirs + (size_t)kg*VC + cg);
                else if (kg < KTOT)
                    val = *reinterpret_cast<const float2*>(shapes + (size_t)(kg-NP)*VC + cg);
            }
            reinterpret_cast<float2*>(s_pd)[i] = val;
        }
        __syncthreads();

        #pragma unroll
        for (int k = 0; k < 32; ++k) {
            const u64* pfr = s_pf2 + k*32 + (tb<<2);
            u64 pb0 = pfr[0], pb1 = pfr[1], pb2 = pfr[2], pb3 = pfr[3];
            const u64* dvp = reinterpret_cast<const u64*>(s_pd + k*96 + tv*6);
            u64 d0 = dvp[0], d1 = dvp[1], d2 = dvp[2];
            acc2[0]  = ffma2(pb0, d0, acc2[0]);
            acc2[1]  = ffma2(pb0, d1, acc2[1]);
            acc2[2]  = ffma2(pb0, d2, acc2[2]);
            acc2[3]  = ffma2(pb1, d0, acc2[3]);
            acc2[4]  = ffma2(pb1, d1, acc2[4]);
            acc2[5]  = ffma2(pb1, d2, acc2[5]);
            acc2[6]  = ffma2(pb2, d0, acc2[6]);
            acc2[7]  = ffma2(pb2, d1, acc2[7]);
            acc2[8]  = ffma2(pb2, d2, acc2[8]);
            acc2[9]  = ffma2(pb3, d0, acc2[9]);
            acc2[10] = ffma2(pb3, d1, acc2[10]);
            acc2[11] = ffma2(pb3, d2, acc2[11]);
        }
        __syncthreads();
    }

    // ---- epilogue: reload smem union with A' (32 batches), weights, template
    float4* sA4 = reinterpret_cast<float4*>(smem);                 // [32][72] float4
    const float4* gA4 = reinterpret_cast<const float4*>(g_A + b0*(NJ*12));
    #pragma unroll
    for (int i = 0; i < 18; ++i) sA4[tid + 128*i] = gA4[tid + 128*i];
    float* s_w  = smem + 9216;   // [32][24]
    float* s_vt = smem + 9984;   // [96]
    #pragma unroll
    for (int i = tid; i < 768; i += 128) {
        int v = v0 + i/24;
        s_w[i] = (v < VV) ? lbs[v*NJ + (i % 24)] : 0.f;
    }
    if (tid < 96) {
        int cg = col0 + tid;
        s_vt[tid] = (cg < VC) ? vtempl[cg] : 0.f;
    }
    __syncthreads();

    #pragma unroll
    for (int bb = 0; bb < 4; ++bb) {
        const int bl = (tb << 2) + bb;
        const float4* Ab = reinterpret_cast<const float4*>(smem) + bl*72;
        u64 T0[6], T1[6];
        #pragma unroll
        for (int i = 0; i < 6; ++i) { T0[i] = z2; T1[i] = z2; }
        #pragma unroll
        for (int j = 0; j < NJ; ++j) {
            float4 a0 = Ab[j*3 + 0];
            float4 a1 = Ab[j*3 + 1];
            float4 a2 = Ab[j*3 + 2];
            u64 a0lo = pack2(a0.x, a0.y), a0hi = pack2(a0.z, a0.w);
            u64 a1lo = pack2(a1.x, a1.y), a1hi = pack2(a1.z, a1.w);
            u64 a2lo = pack2(a2.x, a2.y), a2hi = pack2(a2.z, a2.w);
            float w0 = s_w[(tv*2 + 0)*24 + j];
            float w1 = s_w[(tv*2 + 1)*24 + j];
            u64 w0d = pack2(w0, w0);
            u64 w1d = pack2(w1, w1);
            T0[0] = ffma2(w0d, a0lo, T0[0]); T0[1] = ffma2(w0d, a0hi, T0[1]);
            T0[2] = ffma2(w0d, a1lo, T0[2]); T0[3] = ffma2(w0d, a1hi, T0[3]);
            T0[4] = ffma2(w0d, a2lo, T0[4]); T0[5] = ffma2(w0d, a2hi, T0[5]);
            T1[0] = ffma2(w1d, a0lo, T1[0]); T1[1] = ffma2(w1d, a0hi, T1[1]);
            T1[2] = ffma2(w1d, a1lo, T1[2]); T1[3] = ffma2(w1d, a1hi, T1[3]);
            T1[4] = ffma2(w1d, a2lo, T1[4]); T1[5] = ffma2(w1d, a2hi, T1[5]);
        }
        const int b = b0 + bl;
        // unpack accumulated v_posed offsets: pairs are (x0,y0)(z0,x1)(y1,z1)
        float2 p0 = unpack2(acc2[bb*3 + 0]);
        float2 p1 = unpack2(acc2[bb*3 + 1]);
        float2 p2 = unpack2(acc2[bb*3 + 2]);
        {
            int vg = v0 + tv*2;
            if (vg < VV) {
                float x = p0.x + s_vt[tv*6+0];
                float y = p0.y + s_vt[tv*6+1];
                float z = p1.x + s_vt[tv*6+2];
                float2 r0 = unpack2(T0[0]), r1 = unpack2(T0[1]);
                float2 r2 = unpack2(T0[2]), r3 = unpack2(T0[3]);
                float2 r4 = unpack2(T0[4]), r5 = unpack2(T0[5]);
                float* o = out + (size_t)b*VC + vg*3;
                o[0] = r0.x*x + r0.y*y + r1.x*z + r1.y;
                o[1] = r2.x*x + r2.y*y + r3.x*z + r3.y;
                o[2] = r4.x*x + r4.y*y + r5.x*z + r5.y;
            }
        }
        {
            int vg = v0 + tv*2 + 1;
            if (vg < VV) {
                float x = p1.y + s_vt[tv*6+3];
                float y = p2.x + s_vt[tv*6+4];
                float z = p2.y + s_vt[tv*6+5];
                float2 r0 = unpack2(T1[0]), r1 = unpack2(T1[1]);
                float2 r2 = unpack2(T1[2]), r3 = unpack2(T1[3]);
                float2 r4 = unpack2(T1[4]), r5 = unpack2(T1[5]);
                float* o = out + (size_t)b*VC + vg*3;
                o[0] = r0.x*x + r0.y*y + r1.x*z + r1.y;
                o[1] = r2.x*x + r2.y*y + r3.x*z + r3.y;
                o[2] = r4.x*x + r4.y*y + r5.x*z + r5.y;
            }
        }
    }
}

// ---------------------------------------------------------------------------
// Kernel 3a: joints partials. grid (14 V-chunks, 64 batch-tiles of 8), 256 thr.
// ---------------------------------------------------------------------------
__global__ void __launch_bounds__(256) k_jnt_part(const float* __restrict__ outv,
                                                  const float* __restrict__ jreg)
{
    __shared__ float s_jr[512 * NJO];
    const int chunk = blockIdx.x;
    const int v0 = chunk * 512;
    for (int i = threadIdx.x; i < 512*NJO; i += 256) {
        int v = v0 + i / NJO;
        s_jr[i] = (v < VV) ? jreg[v*NJO + (i % NJO)] : 0.f;
    }
    __syncthreads();

    const int bl = threadIdx.x >> 5, lane = threadIdx.x & 31;
    const int b = blockIdx.y * 8 + bl;

    float acc[57];
    #pragma unroll
    for (int i = 0; i < 57; ++i) acc[i] = 0.f;

    #pragma unroll 4
    for (int i = 0; i < 16; ++i) {
        int vl = lane + i*32;
        int vg = v0 + vl;
        if (vg < VV) {
            const float* p = outv + (size_t)b*VC + vg*3;
            float x = p[0], y = p[1], z = p[2];
            #pragma unroll
            for (int j = 0; j < NJO; ++j) {
                float r = s_jr[vl*NJO + j];
                acc[j*3+0] = fmaf(r, x, acc[j*3+0]);
                acc[j*3+1] = fmaf(r, y, acc[j*3+1]);
                acc[j*3+2] = fmaf(r, z, acc[j*3+2]);
            }
        }
    }
    #pragma unroll
    for (int m = 16; m > 0; m >>= 1)
        #pragma unroll
        for (int i = 0; i < 57; ++i)
            acc[i] += __shfl_xor_sync(0xffffffffu, acc[i], m);

    if (lane == 0) {
        float* dst = g_jpart + (size_t)(b*14 + chunk)*57;
        #pragma unroll
        for (int i = 0; i < 57; ++i) dst[i] = acc[i];
    }
}

__global__ void k_jnt_red(float* __restrict__ out)
{
    int i = blockIdx.x * blockDim.x + threadIdx.x;
    if (i < BB * 57) {
        int b = i / 57, r = i % 57;
        float t = 0.f;
        #pragma unroll
        for (int p = 0; p < 14; ++p) t += g_jpart[(size_t)(b*14 + p)*57 + r];
        out[JNT_OFF + i] = t;
    }
}

// ---------------------------------------------------------------------------
extern "C" void kernel_launch(void* const* d_in, const int* in_sizes, int n_in,
                              void* d_out, int out_size)
{
    const float* inputs   = (const float*)d_in[0];
    const float* v_templ  = (const float*)d_in[1];
    const float* shapes   = (const float*)d_in[2];
    const float* posedirs = (const float*)d_in[3];
    const float* smpl_reg = (const float*)d_in[4];
    const float* lbs_w    = (const float*)d_in[5];
    const float* joint_rg = (const float*)d_in[6];
    float* out = (float*)d_out;

    k_jm<<<dim3(NJ, 8), 128>>>(v_templ, shapes, smpl_reg);
    k_jmred<<<4, 256>>>();

    k_rot<<<(BB*NJ + 255)/256, 256>>>(inputs, out);
    k_chain<<<16, 96>>>(inputs, out);

    k_main<<<dim3(216, 16), 128>>>(posedirs, shapes, lbs_w, v_templ, out);

    k_jnt_part<<<dim3(14, 64), 256>>>(out, joint_rg);
    k_jnt_red<<<(BB*57 + 255)/256, 256>>>(out);
}